// round 15
// baseline (speedup 1.0000x reference)
#include <cuda_runtime.h>
#include <cuda_bf16.h>
#include <math.h>
#include <stdint.h>

// Problem constants (fixed by the dataset)
#define B_   16384
#define E_   128
#define S_   512
#define VOC_ 1000000

#define NPREP 32
#define NGEMM 512                     // 128 row-tiles x 4 col-tiles
#define NTRUE 256                     // 64 true rows each
#define NTOT  (NPREP + NGEMM + NTRUE) // 800

#define TILE_BYTES 32768              // 128 rows x 128 bf16 (256B/row)
#define DYN_SMEM (2 * TILE_BYTES)

// ---- device scratch (no allocations allowed) ----
__device__ uint32_t g_Bsw[4 * TILE_BYTES / 4];   // swizzled bf16 B tiles
__device__ float g_corr[S_];
__device__ float g_part[NTOT];
__device__ unsigned int g_flag[4];    // per-colTile readiness (8 prep blocks each)
__device__ unsigned int g_done;       // ticket; last block resets everything

__device__ __forceinline__ uint32_t smem_u32(const void* p) {
    uint32_t a;
    asm("{ .reg .u64 t; cvta.to.shared.u64 t, %1; cvt.u32.u64 %0, t; }"
        : "=r"(a) : "l"(p));
    return a;
}

// Swizzled tile layout: [row r][16B chunk c], phys chunk = c ^ (r&7).
__device__ __forceinline__ uint32_t tile_off(int r, int c) {
    return (uint32_t)(r * 256 + ((c ^ (r & 7)) << 4));
}

// -------------------------------------------------------------------------
// Index dtype detection (per-block, reads first 2KB = valid for both
// int32[512] and int64[512]). int32 misread as int64 => OOB => int32.
// -------------------------------------------------------------------------
__device__ __forceinline__ int detect64(const void* sampled) {
    long long v = ((const long long*)sampled)[threadIdx.x];
    return !__syncthreads_or(v < 0 || v >= (long long)VOC_);
}
__device__ __forceinline__ int load_id(const void* p, int i, int idx64) {
    long long v;
    if (idx64) v = ((const long long*)p)[i];
    else       v = (long long)((const int*)p)[i];
    if (v < 0) v = 0;
    if (v >= VOC_) v = VOC_ - 1;
    return (int)v;
}

// -------------------------------------------------------------------------
// Reference-faithful -log(expected_count(id)), fp64-CR path (512 sampled ids
// only — these carry full weight in the loss).
// -------------------------------------------------------------------------
__device__ __forceinline__ float neg_log_expected(int id) {
    double cd = (double)id;
    float l2 = (float)log(cd + 2.0);
    float l1 = (float)log(cd + 1.0);
    float denom = (float)log((double)VOC_ + 1.0);
    float p = (l2 - l1) / denom;
    float lp = log1pf(-p);
    float e  = -expm1f(512.0f * lp);
    return -logf(e);
}

// Fast f32 path for LABEL corrections (sensitivity |sigmoid(x)-1| ~ e^-9 in
// the cancellation regime; accurate where it matters). Clamped vs inf.
__device__ __forceinline__ float neg_log_expected_f32(int id) {
    float c  = (float)id;
    float l2 = logf(c + 2.0f);
    float l1 = logf(c + 1.0f);
    float p  = (l2 - l1) * (1.0f / 13.815512f);
    float lp = log1pf(-fminf(p, 0.9999999f));
    float e  = -expm1f(512.0f * lp);
    e = fmaxf(e, 1e-37f);
    return -logf(e);
}

// MUFU softplus: max(x,0) + ln2*lg2(1 + ex2(-|x|*log2e)).
__device__ __forceinline__ float softplus_mufu(float x) {
    float mx = fmaxf(x, 0.0f);
    float y  = fabsf(x) * -1.4426950408889634f;
    float t, l;
    asm("ex2.approx.ftz.f32 %0, %1;" : "=f"(t) : "f"(y));
    asm("lg2.approx.ftz.f32 %0, %1;" : "=f"(l) : "f"(1.0f + t));
    return fmaf(0.69314718055994531f, l, mx);
}

__device__ __forceinline__ uint32_t pack_bf(float a, float b) {
    __nv_bfloat162 h = __floats2bfloat162_rn(a, b);
    return *reinterpret_cast<uint32_t*>(&h);
}

#define LDMX4(r0, r1, r2, r3, addr) \
    asm volatile("ldmatrix.sync.aligned.m8n8.x4.shared.b16 {%0,%1,%2,%3}, [%4];" \
                 : "=r"(r0), "=r"(r1), "=r"(r2), "=r"(r3) : "r"(addr))

#define MMA16816(c, a, b0, b1) \
    asm volatile("mma.sync.aligned.m16n8k16.row.col.f32.bf16.bf16.f32 " \
                 "{%0,%1,%2,%3}, {%4,%5,%6,%7}, {%8,%9}, {%0,%1,%2,%3};" \
                 : "+f"((c)[0]), "+f"((c)[1]), "+f"((c)[2]), "+f"((c)[3]) \
                 : "r"((a)[0]), "r"((a)[1]), "r"((a)[2]), "r"((a)[3]), \
                   "r"(b0), "r"(b1))

// -------------------------------------------------------------------------
// Single fused kernel, grid = 800, block = 256, dyn smem = 64KB, occ 3.
//   bx [0,32):    prep — gather B rows -> g_Bsw + sampled corr, set flag
//   bx [32,544):  GEMM 128x128 tile (stage A, spin flag, stage B, 2x 32-col
//                 mainloop+epilogue passes)
//   bx [544,800): true-class loss, 64 rows each
//   last ticket:  deterministic double reduction + state reset
// -------------------------------------------------------------------------
__global__ __launch_bounds__(256, 3)
void k_fused(const float* __restrict__ P, const float* __restrict__ W,
             const float* __restrict__ bias, const void* __restrict__ labels,
             const void* __restrict__ sampled, float* __restrict__ out) {
    __shared__ float red[8];
    __shared__ double dred[256];
    __shared__ unsigned int ticket;
    extern __shared__ char dyn[];

    const int bx = blockIdx.x;
    const int tid = threadIdx.x, lane = tid & 31, wid = tid >> 5;
    float partial = 0.0f;

    if (bx < NPREP) {
        // ---- prep: 16 sampled rows per block ----
        int idx64 = detect64(sampled);
        int sl = tid >> 4;               // 0..15
        int kg = tid & 15;               // 16B k-chunk
        int s  = bx * 16 + sl;
        int id = load_id(sampled, s, idx64);
        const float* src = W + (size_t)id * E_ + kg * 8;
        float4 v0 = *(const float4*)src;
        float4 v1 = *(const float4*)(src + 4);
        uint4 u;
        u.x = pack_bf(v0.x, v0.y); u.y = pack_bf(v0.z, v0.w);
        u.z = pack_bf(v1.x, v1.y); u.w = pack_bf(v1.z, v1.w);
        int colTile = s >> 7, n = s & 127;
        *(uint4*)((char*)g_Bsw + colTile * TILE_BYTES + tile_off(n, kg)) = u;
        if (tid < 16) {
            int s2 = bx * 16 + tid;
            int id2 = load_id(sampled, s2, idx64);
            g_corr[s2] = bias[id2] + neg_log_expected(id2);
        }
        __syncthreads();
        __threadfence();
        if (tid == 0) atomicAdd(&g_flag[bx >> 3], 1u);   // 8 blocks per colTile
        partial = 0.0f;
    } else if (bx < NPREP + NGEMM) {
        const int tile = bx - NPREP;
        const int rowTile = tile >> 2, colTile = tile & 3;
        char* Abuf = dyn;
        char* Bbuf = dyn + TILE_BYTES;

        // Stage A first (overlaps prep running elsewhere on the chip).
        const float* Abase = P + (size_t)rowTile * 128 * E_;
#pragma unroll
        for (int i = 0; i < 8; i++) {
            int idx = tid + 256 * i;               // 0..2047
            int r = idx >> 4, c = idx & 15;
            const float* src = Abase + (size_t)r * E_ + c * 8;
            float4 v0 = *(const float4*)src;
            float4 v1 = *(const float4*)(src + 4);
            uint4 u;
            u.x = pack_bf(v0.x, v0.y); u.y = pack_bf(v0.z, v0.w);
            u.z = pack_bf(v1.x, v1.y); u.w = pack_bf(v1.z, v1.w);
            *(uint4*)(Abuf + tile_off(r, c)) = u;
        }

        // Acquire the colTile's B data + corr.
        if (tid == 0) {
            unsigned int v;
            do {
                asm volatile("ld.acquire.gpu.u32 %0, [%1];"
                             : "=r"(v) : "l"(&g_flag[colTile]) : "memory");
            } while (v < 8u);
        }
        __syncthreads();

        const uint4* Bsrc = (const uint4*)((const char*)g_Bsw + colTile * TILE_BYTES);
#pragma unroll
        for (int i = 0; i < 8; i++)
            ((uint4*)Bbuf)[tid + 256 * i] = Bsrc[tid + 256 * i];
        __syncthreads();

        const int warpRow = wid & 3;          // m offset *32
        const int warpCol = wid >> 2;         // n offset *64 (split in 2 passes)
        const int lrow = lane & 15;
        const int lhi  = lane >> 4;
        const int q    = lane & 3;

        const uint32_t a_s = smem_u32(Abuf);
        const uint32_t b_s = smem_u32(Bbuf);

        int arow[2];
#pragma unroll
        for (int mi = 0; mi < 2; mi++) arow[mi] = warpRow * 32 + mi * 16 + lrow;

        float lsum = 0.0f;
#pragma unroll
        for (int pass = 0; pass < 2; pass++) {
            int brow[2];
#pragma unroll
            for (int nj = 0; nj < 2; nj++)
                brow[nj] = warpCol * 64 + pass * 32 + nj * 16 + lrow;

            float acc[2][4][4];
#pragma unroll
            for (int mi = 0; mi < 2; mi++)
#pragma unroll
                for (int ni = 0; ni < 4; ni++)
#pragma unroll
                    for (int r = 0; r < 4; r++) acc[mi][ni][r] = 0.0f;

#pragma unroll
            for (int ks = 0; ks < 8; ks++) {
                const int chunk = ks * 2 + lhi;
                uint32_t a[2][4];
#pragma unroll
                for (int mi = 0; mi < 2; mi++) {
                    uint32_t addr = a_s + (uint32_t)(arow[mi] * 256
                                   + ((chunk ^ (arow[mi] & 7)) << 4));
                    LDMX4(a[mi][0], a[mi][1], a[mi][2], a[mi][3], addr);
                }
                uint32_t bb[2][4];
#pragma unroll
                for (int nj = 0; nj < 2; nj++) {
                    uint32_t addr = b_s + (uint32_t)(brow[nj] * 256
                                   + ((chunk ^ (brow[nj] & 7)) << 4));
                    LDMX4(bb[nj][0], bb[nj][1], bb[nj][2], bb[nj][3], addr);
                }
#pragma unroll
                for (int mi = 0; mi < 2; mi++)
#pragma unroll
                    for (int ni = 0; ni < 4; ni++)
                        MMA16816(acc[mi][ni], a[mi],
                                 bb[ni >> 1][ni & 1], bb[ni >> 1][2 + (ni & 1)]);
            }

            // Epilogue for this 32-col half.
            const float* corrB = g_corr + colTile * 128 + warpCol * 64 + pass * 32;
#pragma unroll
            for (int ni = 0; ni < 4; ni++) {
                float c0 = corrB[ni * 8 + q * 2];
                float c1 = corrB[ni * 8 + q * 2 + 1];
#pragma unroll
                for (int mi = 0; mi < 2; mi++) {
                    lsum += softplus_mufu(acc[mi][ni][0] + c0);
                    lsum += softplus_mufu(acc[mi][ni][1] + c1);
                    lsum += softplus_mufu(acc[mi][ni][2] + c0);
                    lsum += softplus_mufu(acc[mi][ni][3] + c1);
                }
            }
        }
        partial = lsum;
    } else {
        // ---- true-class loss: 64 rows per block, 8 rows per warp ----
        int idx64 = detect64(sampled);
        const int rowbase = (bx - NPREP - NGEMM) * 64 + wid * 8;

        int cid = 0;
        float mycorr = 0.0f;
        if (lane < 8) {
            cid = load_id(labels, rowbase + lane, idx64);
            mycorr = bias[cid] + neg_log_expected_f32(cid);
        }

        float wsum = 0.0f;
        int id0 = __shfl_sync(0xFFFFFFFFu, cid, 0);
        float4 p4 = *(const float4*)(P + (size_t)rowbase * E_ + lane * 4);
        float4 w4 = *(const float4*)(W + (size_t)id0 * E_ + lane * 4);
#pragma unroll
        for (int i = 0; i < 8; i++) {
            float4 np, nw;
            if (i < 7) {
                int idn = __shfl_sync(0xFFFFFFFFu, cid, i + 1);
                np = *(const float4*)(P + (size_t)(rowbase + i + 1) * E_ + lane * 4);
                nw = *(const float4*)(W + (size_t)idn * E_ + lane * 4);
            } else {
                np = make_float4(0.f, 0.f, 0.f, 0.f);
                nw = np;
            }
            float d = p4.x * w4.x + p4.y * w4.y + p4.z * w4.z + p4.w * w4.w;
#pragma unroll
            for (int off = 16; off > 0; off >>= 1)
                d += __shfl_xor_sync(0xFFFFFFFFu, d, off);
            float ci = __shfl_sync(0xFFFFFFFFu, mycorr, i);
            if (lane == 0) {
                float x = d + ci;
                wsum += softplus_mufu(x) - x;   // sce(x, z=1)
            }
            p4 = np; w4 = nw;
        }
        partial = (lane == 0) ? wsum : 0.0f;
    }

    // Block reduction: warp shuffle + one cross-warp stage.
#pragma unroll
    for (int off = 16; off > 0; off >>= 1)
        partial += __shfl_xor_sync(0xFFFFFFFFu, partial, off);
    if (lane == 0) red[wid] = partial;
    __syncthreads();
    if (tid == 0) {
        float t = 0.0f;
#pragma unroll
        for (int i = 0; i < 8; i++) t += red[i];
        g_part[bx] = t;
    }

    // Last-block deterministic final reduction + state reset for replay.
    __threadfence();
    if (tid == 0) ticket = atomicAdd(&g_done, 1u);
    __syncthreads();
    if (ticket == NTOT - 1) {
        __threadfence();
        double s = 0.0;
        for (int i = tid; i < NTOT; i += 256) s += (double)g_part[i];
        dred[tid] = s;
        __syncthreads();
#pragma unroll
        for (int k = 128; k > 0; k >>= 1) {
            if (tid < k) dred[tid] += dred[tid + k];
            __syncthreads();
        }
        if (tid == 0) {
            out[0] = (float)(dred[0] / (double)B_);
            g_flag[0] = 0; g_flag[1] = 0; g_flag[2] = 0; g_flag[3] = 0;
            __threadfence();
            g_done = 0;                  // reset for next graph replay
        }
    }
}

// -------------------------------------------------------------------------
extern "C" void kernel_launch(void* const* d_in, const int* in_sizes, int n_in,
                              void* d_out, int out_size) {
    const float* pred    = (const float*)d_in[0];   // [B, E]
    const float* weights = (const float*)d_in[1];   // [V, E]
    const float* biases  = (const float*)d_in[2];   // [V]
    const void*  labels  = d_in[3];                 // [B, 1] int32 or int64
    const void*  sampled = d_in[4];                 // [S]
    float* out = (float*)d_out;

    static int attr_done = 0;
    if (!attr_done) {
        cudaFuncSetAttribute(k_fused, cudaFuncAttributeMaxDynamicSharedMemorySize,
                             DYN_SMEM);
        attr_done = 1;
    }

    k_fused<<<NTOT, 256, DYN_SMEM>>>(pred, weights, biases, labels, sampled, out);
}

// round 16
// speedup vs baseline: 1.2220x; 1.2220x over previous
#include <cuda_runtime.h>
#include <cuda_bf16.h>
#include <math.h>
#include <stdint.h>

// Problem constants (fixed by the dataset)
#define B_   16384
#define E_   128
#define S_   512
#define VOC_ 1000000

#define NPREP 32
#define NGEMM 512                     // 128 row-tiles x 4 col-tiles
#define NTRUE 256                     // 64 true rows each
#define NTOT  (NPREP + NGEMM + NTRUE) // 800

#define TILE_BYTES 32768              // 128 rows x 128 bf16 (256B/row)
#define DYN_SMEM (2 * TILE_BYTES)

// ---- device scratch (no allocations allowed) ----
__device__ uint32_t g_Bsw[4 * TILE_BYTES / 4];   // swizzled bf16 B tiles
__device__ float g_corr[S_];
__device__ float g_part[NTOT];
__device__ unsigned int g_flag[4];    // per-colTile readiness (8 prep blocks each)
__device__ unsigned int g_done;       // ticket; last block resets everything

__device__ __forceinline__ uint32_t smem_u32(const void* p) {
    uint32_t a;
    asm("{ .reg .u64 t; cvta.to.shared.u64 t, %1; cvt.u32.u64 %0, t; }"
        : "=r"(a) : "l"(p));
    return a;
}

// Swizzled tile layout: [row r][16B chunk c], phys chunk = c ^ (r&7).
__device__ __forceinline__ uint32_t tile_off(int r, int c) {
    return (uint32_t)(r * 256 + ((c ^ (r & 7)) << 4));
}

// -------------------------------------------------------------------------
// Index dtype detection (per-block, reads first 2KB = valid for both
// int32[512] and int64[512]). int32 misread as int64 => OOB => int32.
// -------------------------------------------------------------------------
__device__ __forceinline__ int detect64(const void* sampled) {
    long long v = ((const long long*)sampled)[threadIdx.x];
    return !__syncthreads_or(v < 0 || v >= (long long)VOC_);
}
__device__ __forceinline__ int load_id(const void* p, int i, int idx64) {
    long long v;
    if (idx64) v = ((const long long*)p)[i];
    else       v = (long long)((const int*)p)[i];
    if (v < 0) v = 0;
    if (v >= VOC_) v = VOC_ - 1;
    return (int)v;
}

// -------------------------------------------------------------------------
// Reference-faithful -log(expected_count(id)), fp64-CR path (512 sampled
// ids only — these carry full weight in the loss).
// -------------------------------------------------------------------------
__device__ __forceinline__ float neg_log_expected(int id) {
    double cd = (double)id;
    float l2 = (float)log(cd + 2.0);
    float l1 = (float)log(cd + 1.0);
    float denom = (float)log((double)VOC_ + 1.0);
    float p = (l2 - l1) / denom;
    float lp = log1pf(-p);
    float e  = -expm1f(512.0f * lp);
    return -logf(e);
}

// Fast f32 path for LABEL corrections (loss sensitivity |sigmoid(x)-1| is
// ~e^-9 exactly in the cancellation regime; accurate where it matters).
__device__ __forceinline__ float neg_log_expected_f32(int id) {
    float c  = (float)id;
    float l2 = logf(c + 2.0f);
    float l1 = logf(c + 1.0f);
    float p  = (l2 - l1) * (1.0f / 13.815512f);
    float lp = log1pf(-fminf(p, 0.9999999f));
    float e  = -expm1f(512.0f * lp);
    e = fmaxf(e, 1e-37f);
    return -logf(e);
}

// MUFU softplus: max(x,0) + ln2*lg2(1 + ex2(-|x|*log2e)).
__device__ __forceinline__ float softplus_mufu(float x) {
    float mx = fmaxf(x, 0.0f);
    float y  = fabsf(x) * -1.4426950408889634f;
    float t, l;
    asm("ex2.approx.ftz.f32 %0, %1;" : "=f"(t) : "f"(y));
    asm("lg2.approx.ftz.f32 %0, %1;" : "=f"(l) : "f"(1.0f + t));
    return fmaf(0.69314718055994531f, l, mx);
}

__device__ __forceinline__ uint32_t pack_bf(float a, float b) {
    __nv_bfloat162 h = __floats2bfloat162_rn(a, b);
    return *reinterpret_cast<uint32_t*>(&h);
}

#define LDMX4(r0, r1, r2, r3, addr) \
    asm volatile("ldmatrix.sync.aligned.m8n8.x4.shared.b16 {%0,%1,%2,%3}, [%4];" \
                 : "=r"(r0), "=r"(r1), "=r"(r2), "=r"(r3) : "r"(addr))

#define MMA16816(c, a, b0, b1) \
    asm volatile("mma.sync.aligned.m16n8k16.row.col.f32.bf16.bf16.f32 " \
                 "{%0,%1,%2,%3}, {%4,%5,%6,%7}, {%8,%9}, {%0,%1,%2,%3};" \
                 : "+f"((c)[0]), "+f"((c)[1]), "+f"((c)[2]), "+f"((c)[3]) \
                 : "r"((a)[0]), "r"((a)[1]), "r"((a)[2]), "r"((a)[3]), \
                   "r"(b0), "r"(b1))

// -------------------------------------------------------------------------
// Single fused kernel, grid = 800, block = 256 (8 warps 4x2), occ 2.
//   bx [0,32):    prep — gather B rows -> g_Bsw + sampled corr, set flag
//   bx [32,544):  GEMM 128x128 tile — R14's proven single-pass mainloop
//                 (stage A first, spin colTile flag, stage B, 8 k-steps)
//   bx [544,800): true-class loss, 64 rows each
//   last ticket:  deterministic double reduction + state reset
// -------------------------------------------------------------------------
__global__ __launch_bounds__(256, 2)
void k_fused(const float* __restrict__ P, const float* __restrict__ W,
             const float* __restrict__ bias, const void* __restrict__ labels,
             const void* __restrict__ sampled, float* __restrict__ out) {
    __shared__ float red[8];
    __shared__ double dred[256];
    __shared__ unsigned int ticket;
    extern __shared__ char dyn[];

    const int bx = blockIdx.x;
    const int tid = threadIdx.x, lane = tid & 31, wid = tid >> 5;
    float partial = 0.0f;

    if (bx < NPREP) {
        // ---- prep: 16 sampled rows per block ----
        int idx64 = detect64(sampled);
        int sl = tid >> 4;               // 0..15
        int kg = tid & 15;               // 16B k-chunk
        int s  = bx * 16 + sl;
        int id = load_id(sampled, s, idx64);
        const float* src = W + (size_t)id * E_ + kg * 8;
        float4 v0 = *(const float4*)src;
        float4 v1 = *(const float4*)(src + 4);
        uint4 u;
        u.x = pack_bf(v0.x, v0.y); u.y = pack_bf(v0.z, v0.w);
        u.z = pack_bf(v1.x, v1.y); u.w = pack_bf(v1.z, v1.w);
        int colTile = s >> 7, n = s & 127;
        *(uint4*)((char*)g_Bsw + colTile * TILE_BYTES + tile_off(n, kg)) = u;
        if (tid < 16) {
            int s2 = bx * 16 + tid;
            int id2 = load_id(sampled, s2, idx64);
            g_corr[s2] = bias[id2] + neg_log_expected(id2);
        }
        __syncthreads();
        __threadfence();
        if (tid == 0) atomicAdd(&g_flag[bx >> 3], 1u);   // 8 blocks per colTile
    } else if (bx < NPREP + NGEMM) {
        const int tile = bx - NPREP;
        const int rowTile = tile >> 2, colTile = tile & 3;
        char* Abuf = dyn;
        char* Bbuf = dyn + TILE_BYTES;

        // Stage A first (overlaps prep blocks running elsewhere).
        const float* Abase = P + (size_t)rowTile * 128 * E_;
#pragma unroll
        for (int i = 0; i < 8; i++) {
            int idx = tid + 256 * i;               // 0..2047
            int r = idx >> 4, c = idx & 15;
            const float* src = Abase + (size_t)r * E_ + c * 8;
            float4 v0 = *(const float4*)src;
            float4 v1 = *(const float4*)(src + 4);
            uint4 u;
            u.x = pack_bf(v0.x, v0.y); u.y = pack_bf(v0.z, v0.w);
            u.z = pack_bf(v1.x, v1.y); u.w = pack_bf(v1.z, v1.w);
            *(uint4*)(Abuf + tile_off(r, c)) = u;
        }

        // Acquire this colTile's B data + corr (usually already released).
        if (tid == 0) {
            unsigned int v;
            do {
                asm volatile("ld.acquire.gpu.u32 %0, [%1];"
                             : "=r"(v) : "l"(&g_flag[colTile]) : "memory");
            } while (v < 8u);
        }
        __syncthreads();

        const uint4* Bsrc = (const uint4*)((const char*)g_Bsw + colTile * TILE_BYTES);
#pragma unroll
        for (int i = 0; i < 8; i++)
            ((uint4*)Bbuf)[tid + 256 * i] = Bsrc[tid + 256 * i];
        __syncthreads();

        const int warpRow = wid & 3;          // m offset *32
        const int warpCol = wid >> 2;         // n offset *64
        const int lrow = lane & 15;
        const int lhi  = lane >> 4;

        const uint32_t a_s = smem_u32(Abuf);
        const uint32_t b_s = smem_u32(Bbuf);

        int arow[2], brow[4];
#pragma unroll
        for (int mi = 0; mi < 2; mi++) arow[mi] = warpRow * 32 + mi * 16 + lrow;
#pragma unroll
        for (int nj = 0; nj < 4; nj++) brow[nj] = warpCol * 64 + nj * 16 + lrow;

        float acc[2][8][4];
#pragma unroll
        for (int mi = 0; mi < 2; mi++)
#pragma unroll
            for (int ni = 0; ni < 8; ni++)
#pragma unroll
                for (int r = 0; r < 4; r++) acc[mi][ni][r] = 0.0f;

#pragma unroll
        for (int ks = 0; ks < 8; ks++) {
            const int chunk = ks * 2 + lhi;
            uint32_t a[2][4];
#pragma unroll
            for (int mi = 0; mi < 2; mi++) {
                uint32_t addr = a_s + (uint32_t)(arow[mi] * 256
                               + ((chunk ^ (arow[mi] & 7)) << 4));
                LDMX4(a[mi][0], a[mi][1], a[mi][2], a[mi][3], addr);
            }
            uint32_t bb[4][4];
#pragma unroll
            for (int nj = 0; nj < 4; nj++) {
                uint32_t addr = b_s + (uint32_t)(brow[nj] * 256
                               + ((chunk ^ (brow[nj] & 7)) << 4));
                LDMX4(bb[nj][0], bb[nj][1], bb[nj][2], bb[nj][3], addr);
            }
#pragma unroll
            for (int mi = 0; mi < 2; mi++)
#pragma unroll
                for (int ni = 0; ni < 8; ni++)
                    MMA16816(acc[mi][ni], a[mi],
                             bb[ni >> 1][ni & 1], bb[ni >> 1][2 + (ni & 1)]);
        }

        // Epilogue: cols colTile*128 + warpCol*64 + ni*8 + q*2 (+1)
        const int q = lane & 3;
        const float* corrB = g_corr + colTile * 128 + warpCol * 64;
        float lsum = 0.0f;
#pragma unroll
        for (int ni = 0; ni < 8; ni++) {
            float c0 = corrB[ni * 8 + q * 2];
            float c1 = corrB[ni * 8 + q * 2 + 1];
#pragma unroll
            for (int mi = 0; mi < 2; mi++) {
                lsum += softplus_mufu(acc[mi][ni][0] + c0);
                lsum += softplus_mufu(acc[mi][ni][1] + c1);
                lsum += softplus_mufu(acc[mi][ni][2] + c0);
                lsum += softplus_mufu(acc[mi][ni][3] + c1);
            }
        }
        partial = lsum;
    } else {
        // ---- true-class loss: 64 rows per block, 8 rows per warp ----
        int idx64 = detect64(sampled);
        const int rowbase = (bx - NPREP - NGEMM) * 64 + wid * 8;

        int cid = 0;
        float mycorr = 0.0f;
        if (lane < 8) {
            cid = load_id(labels, rowbase + lane, idx64);
            mycorr = bias[cid] + neg_log_expected_f32(cid);
        }

        float wsum = 0.0f;
        int id0 = __shfl_sync(0xFFFFFFFFu, cid, 0);
        float4 p4 = *(const float4*)(P + (size_t)rowbase * E_ + lane * 4);
        float4 w4 = *(const float4*)(W + (size_t)id0 * E_ + lane * 4);
#pragma unroll
        for (int i = 0; i < 8; i++) {
            float4 np, nw;
            if (i < 7) {
                int idn = __shfl_sync(0xFFFFFFFFu, cid, i + 1);
                np = *(const float4*)(P + (size_t)(rowbase + i + 1) * E_ + lane * 4);
                nw = *(const float4*)(W + (size_t)idn * E_ + lane * 4);
            } else {
                np = make_float4(0.f, 0.f, 0.f, 0.f);
                nw = np;
            }
            float d = p4.x * w4.x + p4.y * w4.y + p4.z * w4.z + p4.w * w4.w;
#pragma unroll
            for (int off = 16; off > 0; off >>= 1)
                d += __shfl_xor_sync(0xFFFFFFFFu, d, off);
            float ci = __shfl_sync(0xFFFFFFFFu, mycorr, i);
            if (lane == 0) {
                float x = d + ci;
                wsum += softplus_mufu(x) - x;   // sce(x, z=1)
            }
            p4 = np; w4 = nw;
        }
        partial = (lane == 0) ? wsum : 0.0f;
    }

    // Block reduction: warp shuffle + one cross-warp stage.
#pragma unroll
    for (int off = 16; off > 0; off >>= 1)
        partial += __shfl_xor_sync(0xFFFFFFFFu, partial, off);
    if (lane == 0) red[wid] = partial;
    __syncthreads();
    if (tid == 0) {
        float t = 0.0f;
#pragma unroll
        for (int i = 0; i < 8; i++) t += red[i];
        g_part[bx] = t;
    }

    // Last-block deterministic final reduction + state reset for replay.
    __threadfence();
    if (tid == 0) ticket = atomicAdd(&g_done, 1u);
    __syncthreads();
    if (ticket == NTOT - 1) {
        __threadfence();
        double s = 0.0;
        for (int i = tid; i < NTOT; i += 256) s += (double)g_part[i];
        dred[tid] = s;
        __syncthreads();
#pragma unroll
        for (int k = 128; k > 0; k >>= 1) {
            if (tid < k) dred[tid] += dred[tid + k];
            __syncthreads();
        }
        if (tid == 0) {
            out[0] = (float)(dred[0] / (double)B_);
            g_flag[0] = 0; g_flag[1] = 0; g_flag[2] = 0; g_flag[3] = 0;
            __threadfence();
            g_done = 0;                  // reset for next graph replay
        }
    }
}

// -------------------------------------------------------------------------
extern "C" void kernel_launch(void* const* d_in, const int* in_sizes, int n_in,
                              void* d_out, int out_size) {
    const float* pred    = (const float*)d_in[0];   // [B, E]
    const float* weights = (const float*)d_in[1];   // [V, E]
    const float* biases  = (const float*)d_in[2];   // [V]
    const void*  labels  = d_in[3];                 // [B, 1] int32 or int64
    const void*  sampled = d_in[4];                 // [S]
    float* out = (float*)d_out;

    static int attr_done = 0;
    if (!attr_done) {
        cudaFuncSetAttribute(k_fused, cudaFuncAttributeMaxDynamicSharedMemorySize,
                             DYN_SMEM);
        attr_done = 1;
    }

    k_fused<<<NTOT, 256, DYN_SMEM>>>(pred, weights, biases, labels, sampled, out);
}